// round 7
// baseline (speedup 1.0000x reference)
#include <cuda_runtime.h>

#define NB   256
#define NT   1024
#define NS   7
#define NH   64
#define NL   4
#define NOUT 3

#define UQ   8                             // timesteps per pipeline interval
#define NBLK (NT / UQ)                     // 128 timestep-blocks
#define NITER (NBLK + 7)                   // pipeline depth: 2 per split stage + output
#define CH   64                            // x-staging chunk (timesteps)
#define XPC  (CH * NS)                     // 448 floats
#define TBLH_FLOATS (3 * 16 * 16 * 64)     // 192 KB
#define TBLO_FLOATS (16 * 16 * 4)          // 4 KB
#define XS_FLOATS   (2 * XPC)              // 3.5 KB
#define PART_FLOATS (2 * 3 * 2 * UQ * 64)  // partial ring: 24 KB
#define SMEM_FLOATS (TBLH_FLOATS + TBLO_FLOATS + XS_FLOATS + PART_FLOATS)
#define MASK_BYTES  (2 * 4 * 2 * UQ * 8)   // 1 KB
#define SMEM_BYTES  (SMEM_FLOATS * 4 + MASK_BYTES)   // 229,888 B

#define ADDX2(out, a, b) \
    asm("add.rn.f32x2 %0, %1, %2;" : "=l"(out) : "l"(a), "l"(b))
typedef unsigned long long ull;

// Neuron ownership: lane owns neurons (2*lane, 2*lane+1).
// maskA bit lane = spike of neuron 2*lane; maskB = neuron 2*lane+1.
// Groups g in [0,8): nibble g of maskA -> inputs {8g, 8g+2, 8g+4, 8g+6}
// Groups g in [8,16): nibble g-8 of maskB -> odd counterparts.
__device__ __forceinline__ int in_neuron(int g, int i) {
    return (g < 8) ? (8 * g + 2 * i) : (8 * (g - 8) + 2 * i + 1);
}

// 8 subset-sum lookups for one 32-bit mask; tb pre-offset by lane*8 (+group base)
__device__ __forceinline__ ull lut8(unsigned m, const char* tb) {
    unsigned e = m & 0x0F0F0F0Fu, o = (m >> 4) & 0x0F0F0F0Fu;
    ull a0 = 0ull, a1 = 0ull;
#pragma unroll
    for (int g = 0; g < 8; ++g) {
        unsigned src = (g & 1) ? o : e;
        unsigned idx = __byte_perm(src, 0, 0x4440 | (g >> 1));
        ull v = *reinterpret_cast<const ull*>(
            tb + ((size_t)g << 12) + ((size_t)idx << 8));
        if (g & 1) { ull r; ADDX2(r, a1, v); a1 = r; }
        else       { ull r; ADDX2(r, a0, v); a0 = r; }
    }
    ull at; ADDX2(at, a0, a1);
    return at;
}

// wid -> role nibble: bit0 = bslot, bits[2:1] = stage, bit3 = isB.
// Chosen so per-SMSP (wid&3) issue load balances:
//   SMSP0/1: s0 + s1A + s2A + s3B   SMSP2/3: s1B + s2B + s3A
#define ROLE_TBL 0xFE7654DC32BA10ULL

__global__ __launch_bounds__(448, 1)
void snn_kernel(const float* __restrict__ x,
                const float* __restrict__ hidden0,
                const float* __restrict__ w1,
                const float* __restrict__ b1,
                const float* __restrict__ w_h,
                const float* __restrict__ b_h,
                const float* __restrict__ w_out,
                const float* __restrict__ b_out,
                float* __restrict__ out_outputs,   // (B,T,OUT)
                float* __restrict__ out_hidden)    // (B,T,L,H)
{
    extern __shared__ float smem[];
    float*  tblH = smem;                                  // [48][16][64]
    float*  tblO = smem + TBLH_FLOATS;                    // [16][16][4]
    float*  xbuf = tblO + TBLO_FLOATS;                    // [2][XPC]
    float2* part = reinterpret_cast<float2*>(xbuf + XS_FLOATS); // [2][3][2][UQ][32]
    uint2 (*mring)[4][2][UQ] =
        reinterpret_cast<uint2 (*)[4][2][UQ]>(smem + SMEM_FLOATS);

    const int tid  = threadIdx.x;
    const int lane = tid & 31;
    const int wid  = tid >> 5;

    const unsigned code  = (unsigned)((ROLE_TBL >> (4 * wid)) & 0xF);
    const int bslot = code & 1;
    const int stage = (code >> 1) & 3;
    const int isB   = (code >> 3) & 1;
    const int b     = blockIdx.x * 2 + bslot;

    // ---- build LUTs (14 warps stripe the 48 (l,g) slices) ----
    {
        for (int lg = wid; lg < 48; lg += 14) {
            const int l = lg >> 4, g = lg & 15;
            float wa[4], wb[4];
#pragma unroll
            for (int i = 0; i < 4; ++i) {
                const int in = in_neuron(g, i);
                wa[i] = w_h[(size_t)(l * NH + 2 * lane)     * NH + in];
                wb[i] = w_h[(size_t)(l * NH + 2 * lane + 1) * NH + in];
            }
            float* dst = tblH + (size_t)(lg * 16) * 64 + 2 * lane;
#pragma unroll
            for (int p = 0; p < 16; ++p) {
                float sa = 0.f, sb = 0.f;
                if (p & 1) { sa += wa[0]; sb += wb[0]; }
                if (p & 2) { sa += wa[1]; sb += wb[1]; }
                if (p & 4) { sa += wa[2]; sb += wb[2]; }
                if (p & 8) { sa += wa[3]; sb += wb[3]; }
                *reinterpret_cast<float2*>(dst + (size_t)p * 64) =
                    make_float2(sa, sb);
            }
        }
        if (tid < 48) {
            const int o = tid >> 4, g = tid & 15;
            float wo[4];
#pragma unroll
            for (int i = 0; i < 4; ++i)
                wo[i] = w_out[o * NH + in_neuron(g, i)];
#pragma unroll
            for (int p = 0; p < 16; ++p) {
                float s = 0.f;
                if (p & 1) s += wo[0];
                if (p & 2) s += wo[1];
                if (p & 4) s += wo[2];
                if (p & 8) s += wo[3];
                tblO[(g * 16 + p) * 4 + o] = s;
            }
        }
    }
    __syncthreads();

    // ---- per-role state ----
    float ma = 0.f, mbv = 0.f;           // membranes (stage0 and B warps)
    if (stage == 0 || isB) {
        const float* h0 = hidden0 + (size_t)b * NT * NL * NH + stage * NH;
        float2 m0 = *reinterpret_cast<const float2*>(h0 + 2 * lane);
        ma = m0.x; mbv = m0.y;
    }

    float w1a[NS], w1b[NS];
    float b1a = 0.f, b1b = 0.f, bo = 0.f, bha = 0.f, bhb = 0.f;
    float xs[14];
    const float* xb = x + (size_t)b * NT * NS;
    float* xw = xbuf + bslot * XPC;
    const int otc = lane / 3, oo = lane - 3 * otc;
    if (stage == 0) {
#pragma unroll
        for (int s = 0; s < NS; ++s) {
            w1a[s] = w1[(2 * lane)     * NS + s];
            w1b[s] = w1[(2 * lane + 1) * NS + s];
        }
        b1a = b1[2 * lane];
        b1b = b1[2 * lane + 1];
        bo  = (lane < 24) ? b_out[oo] : 0.0f;
#pragma unroll
        for (int j = 0; j < 14; ++j) xs[j] = xb[j * 32 + lane];
    } else if (isB) {
        bha = b_h[(stage - 1) * NH + 2 * lane];
        bhb = b_h[(stage - 1) * NH + 2 * lane + 1];
    }

    float* hout = out_hidden  + (size_t)b * NT * NL * NH + stage * NH;
    float* oout = out_outputs + (size_t)b * NT * NOUT;
    // LUT byte base for this stage's slice; A: groups 0-7, B: groups 8-15
    const char* tb = reinterpret_cast<const char*>(
        tblH + (size_t)(stage > 0 ? (stage - 1) : 0) * (16 * 16 * 64))
        + lane * 8 + (isB ? 8 * 4096 : 0);
    // partial ring slice for this (bslot, stage)
    float2* pslice = part + ((size_t)(bslot * 3 + (stage - 1)) * 2) * (UQ * 32);

    ull  rp[UQ];                          // B: register partials for next block
    for (int i = 0; i < NITER; ++i) {
        if (stage == 0) {
            if (i < NBLK) {
                if ((i & 7) == 0) {            // new 64-step x chunk
#pragma unroll
                    for (int j = 0; j < 14; ++j) xw[j * 32 + lane] = xs[j];
                    __syncwarp();
                    const int c = i >> 3;
                    if (c + 1 < NT / CH) {
#pragma unroll
                        for (int j = 0; j < 14; ++j)
                            xs[j] = xb[(c + 1) * XPC + j * 32 + lane];
                    }
                }
#pragma unroll
                for (int tt = 0; tt < UQ; ++tt) {
                    const int t = i * UQ + tt;
                    const float* xt = xw + (t & 63) * NS;
                    float cx = b1a, cy = b1b;
#pragma unroll
                    for (int s = 0; s < NS; ++s) {
                        float xv = xt[s];
                        cx = fmaf(xv, w1a[s], cx);
                        cy = fmaf(xv, w1b[s], cy);
                    }
                    float nx = __fadd_rn(__fmul_rn(0.8f, ma),  cx);
                    float ny = __fadd_rn(__fmul_rn(0.8f, mbv), cy);
                    if (ma  > 1.0f) nx = __fadd_rn(nx, -1.0f);
                    if (mbv > 1.0f) ny = __fadd_rn(ny, -1.0f);
                    ma = nx; mbv = ny;
                    unsigned mA = __ballot_sync(0xffffffffu, nx > 1.0f);
                    unsigned mB = __ballot_sync(0xffffffffu, ny > 1.0f);
                    if (lane == 0) mring[bslot][0][i & 1][tt] = make_uint2(mA, mB);
                    *reinterpret_cast<float2*>(
                        hout + (size_t)t * NL * NH + 2 * lane) = make_float2(ma, mbv);
                }
            }
            if (i >= 7) {                      // output layer: block i-7
                const int j2 = i - 7;
                uint2 m3 = make_uint2(0u, 0u);
                if (lane < 24) m3 = mring[bslot][3][(i - 1) & 1][otc];
                const unsigned eA = m3.x & 0x0F0F0F0Fu, oA = (m3.x >> 4) & 0x0F0F0F0Fu;
                const unsigned eB = m3.y & 0x0F0F0F0Fu, oB = (m3.y >> 4) & 0x0F0F0F0Fu;
                float oacc = bo;
#pragma unroll
                for (int g = 0; g < 16; ++g) {
                    unsigned src = (g < 8) ? ((g & 1) ? oA : eA)
                                           : ((g & 1) ? oB : eB);
                    unsigned idx = __byte_perm(src, 0, 0x4440 | ((g >> 1) & 3));
                    oacc += tblO[(g * 16 + idx) * 4 + oo];
                }
                if (lane < 24) oout[(size_t)j2 * (UQ * NOUT) + lane] = oacc;
            }
        } else if (!isB) {
            // ---- A: lookups for block j, groups 0-7 (mask .x), STS partial
            const int j = i - (2 * stage - 1);
            if (j >= 0 && j < NBLK) {
                const int par = (i - 1) & 1;
                float2* pd = pslice + (size_t)(i & 1) * (UQ * 32) + lane;
#pragma unroll
                for (int tt = 0; tt < UQ; ++tt) {
                    unsigned m = mring[bslot][stage - 1][par][tt].x;
                    ull at = lut8(m, tb);
                    pd[tt * 32] = *reinterpret_cast<float2*>(&at);
                }
            }
        } else {
            // ---- B: combine block jc (reg partial + A's smem partial),
            //         membrane/ballot/store; then lookups for block jc+1
            const int jc = i - 2 * stage;
            if (jc >= 0 && jc < NBLK) {
                const float2* ps = pslice + (size_t)((i - 1) & 1) * (UQ * 32) + lane;
#pragma unroll
                for (int tt = 0; tt < UQ; ++tt) {
                    float2 pa = ps[tt * 32];
                    ull pv = *reinterpret_cast<ull*>(&pa);
                    ull sv; ADDX2(sv, rp[tt], pv);
                    float2 s2 = *reinterpret_cast<float2*>(&sv);
                    float cx = s2.x + bha;
                    float cy = s2.y + bhb;
                    float nx = __fadd_rn(__fmul_rn(0.8f, ma),  cx);
                    float ny = __fadd_rn(__fmul_rn(0.8f, mbv), cy);
                    if (ma  > 1.0f) nx = __fadd_rn(nx, -1.0f);
                    if (mbv > 1.0f) ny = __fadd_rn(ny, -1.0f);
                    ma = nx; mbv = ny;
                    unsigned mA = __ballot_sync(0xffffffffu, nx > 1.0f);
                    unsigned mB = __ballot_sync(0xffffffffu, ny > 1.0f);
                    if (lane == 0)
                        mring[bslot][stage][i & 1][tt] = make_uint2(mA, mB);
                    const int t = jc * UQ + tt;
                    *reinterpret_cast<float2*>(
                        hout + (size_t)t * NL * NH + 2 * lane) = make_float2(ma, mbv);
                }
            }
            const int jn = i - 2 * stage + 1;
            if (jn >= 0 && jn < NBLK) {
                const int par = (i - 1) & 1;
#pragma unroll
                for (int tt = 0; tt < UQ; ++tt) {
                    unsigned m = mring[bslot][stage - 1][par][tt].y;
                    rp[tt] = lut8(m, tb);
                }
            }
        }
        __syncthreads();   // orders mask/partial publish -> next-interval consume
    }
}

// x passthrough: third tuple element of the reference output
__global__ void copy_kernel(const float4* __restrict__ src,
                            float4* __restrict__ dst, int n4)
{
    int i = blockIdx.x * blockDim.x + threadIdx.x;
    if (i < n4) dst[i] = src[i];
}

extern "C" void kernel_launch(void* const* d_in, const int* in_sizes, int n_in,
                              void* d_out, int out_size)
{
    const float* x      = (const float*)d_in[0];
    const float* hidden = (const float*)d_in[1];
    // d_in[2] = prev_obs (unused by reference)
    const float* w1     = (const float*)d_in[3];
    const float* b1     = (const float*)d_in[4];
    const float* w_h    = (const float*)d_in[5];
    const float* b_h    = (const float*)d_in[6];
    const float* w_out  = (const float*)d_in[7];
    const float* b_out  = (const float*)d_in[8];

    float* out         = (float*)d_out;
    float* out_outputs = out;                                    // B*T*OUT
    float* out_hidden  = out_outputs + (size_t)NB * NT * NOUT;   // B*T*L*H
    float* out_x       = out_hidden + (size_t)NB * NT * NL * NH; // B*T*S

    // copy FIRST so ncu (-s 5 -c 1) captures the SNN kernel
    const int n4 = (NB * NT * NS) / 4;
    copy_kernel<<<(n4 + 255) / 256, 256>>>((const float4*)x, (float4*)out_x, n4);

    cudaFuncSetAttribute(snn_kernel,
                         cudaFuncAttributeMaxDynamicSharedMemorySize, SMEM_BYTES);
    snn_kernel<<<NB / 2, 448, SMEM_BYTES>>>(x, hidden, w1, b1, w_h, b_h,
                                            w_out, b_out, out_outputs, out_hidden);
}